// round 10
// baseline (speedup 1.0000x reference)
#include <cuda_runtime.h>
#include <cstdint>

#define BATCH 8
#define HH    64
#define WW_   64
#define TT    4096
#define CC    256
#define DD    512
#define MM    (BATCH * TT)   // 32768

#define NCHAIN 4096
#define NCHUNK 32
#define CHLEN  128

// ---------------- scratch (static device globals; no runtime alloc) ----------
__device__ float g_comb[25 * CC];
__device__ float g_xf[BATCH * TT * CC];     // tf32-rounded activations
__device__ float g_k [BATCH * TT * CC];
__device__ float g_v [BATCH * TT * CC];
__device__ float g_sr[BATCH * TT * CC];
__device__ float g_xs[BATCH * TT * DD];     // tf32-rounded scan output
__device__ float g_sa[NCHUNK * NCHAIN];
__device__ float g_sb[NCHUNK * NCHAIN];
__device__ float g_sp[NCHUNK * NCHAIN];
__device__ float g_pa[NCHUNK * NCHAIN];
__device__ float g_pb[NCHUNK * NCHAIN];
__device__ float g_pp[NCHUNK * NCHAIN];
// tf32-rounded weights
__device__ float g_wk[CC * CC];
__device__ float g_wv[CC * CC];
__device__ float g_wr[CC * CC];
__device__ float g_wo[CC * DD];

__device__ __forceinline__ unsigned f2tf32(float f) {
    unsigned u;
    asm("cvt.rna.tf32.f32 %0, %1;" : "=r"(u) : "f"(f));
    return u;
}
__device__ __forceinline__ float rnd_tf32(float f) {
    return __uint_as_float(f2tf32(f));
}

// ---------------- 0) round weights to tf32 grid ------------------------------
__global__ void round_weights_kernel(const float* __restrict__ Wk,
                                     const float* __restrict__ Wv,
                                     const float* __restrict__ Wr,
                                     const float* __restrict__ Wo)
{
    int i = blockIdx.x * 256 + threadIdx.x;
    if (i < CC * CC) {
        g_wk[i] = rnd_tf32(Wk[i]);
        g_wv[i] = rnd_tf32(Wv[i]);
        g_wr[i] = rnd_tf32(Wr[i]);
    }
    if (i < CC * DD) g_wo[i] = rnd_tf32(Wo[i]);
}

// ---------------- 1) combine identity + 1x1 + 3x3 + 5x5 into one 5x5 ---------
__global__ void combine_weights_kernel(const float* __restrict__ alpha,
                                       const float* __restrict__ cw1,
                                       const float* __restrict__ cw3,
                                       const float* __restrict__ cw5)
{
    int c = threadIdx.x;
    float a0 = alpha[0], a1 = alpha[1], a2 = alpha[2], a3 = alpha[3];
    #pragma unroll
    for (int j = 0; j < 5; j++) {
        #pragma unroll
        for (int i = 0; i < 5; i++) {
            float v = a3 * cw5[c * 25 + j * 5 + i];
            if (j >= 1 && j <= 3 && i >= 1 && i <= 3)
                v += a2 * cw3[c * 9 + (j - 1) * 3 + (i - 1)];
            if (j == 2 && i == 2)
                v += a1 * cw1[c] + a0;
            g_comb[(j * 5 + i) * CC + c] = v;
        }
    }
}

// ---------------- 2) depthwise 5x5 conv; output tf32-rounded -----------------
__global__ __launch_bounds__(256) void omni_conv_kernel(const float* __restrict__ x)
{
    int b  = blockIdx.x >> 6;
    int xc = blockIdx.x & 63;
    int c  = threadIdx.x;

    float wgt[25];
    #pragma unroll
    for (int j = 0; j < 25; j++) wgt[j] = g_comb[j * CC + c];

    const float* xin  = x    + (size_t)b * TT * CC + c;
    float*       xout = g_xf + (size_t)b * TT * CC + (size_t)xc * CC + c;

    float win[5][5];
    #pragma unroll
    for (int i = 0; i < 5; i++) { win[0][i] = 0.f; win[1][i] = 0.f; }
    #pragma unroll
    for (int r = 0; r < 3; r++) {
        #pragma unroll
        for (int i = 0; i < 5; i++) {
            int xx = xc - 2 + i;
            win[2 + r][i] = (xx >= 0 && xx < WW_) ? xin[((size_t)r * WW_ + xx) * CC] : 0.f;
        }
    }

    #pragma unroll 2
    for (int y = 0; y < HH; y++) {
        float acc = 0.f;
        #pragma unroll
        for (int j = 0; j < 5; j++)
            #pragma unroll
            for (int i = 0; i < 5; i++)
                acc = fmaf(wgt[j * 5 + i], win[j][i], acc);
        xout[(size_t)y * WW_ * CC] = rnd_tf32(acc);

        #pragma unroll
        for (int j = 0; j < 4; j++)
            #pragma unroll
            for (int i = 0; i < 5; i++) win[j][i] = win[j + 1][i];
        int row = y + 3;
        #pragma unroll
        for (int i = 0; i < 5; i++) {
            int xx = xc - 2 + i;
            win[4][i] = (row < HH && xx >= 0 && xx < WW_)
                        ? xin[((size_t)row * WW_ + xx) * CC] : 0.f;
        }
    }
}

// ---------------- 3) tf32 mma.sync GEMM, permuted smem, LDS.128 frags --------
// Inputs pre-rounded to tf32 grid -> HW truncation in mma == rna (bit-identical).
// Block 128x128x32, 8 warps (2x4), warp tile 64x32, m16n8k8.
// smem layout per stage, per matrix: [k=0..31][SROW words], where row r of the
// tile is stored at index sidx(r) = (r&~31)|((r&7)<<2)|((r>>3)&3), XOR-swizzled
// by ((k>>4)<<1) so staging STS is bank-conflict-free. Fragment loads become
// LDS.128 (4 per k8 for A, 2 for B).
#define SROW    132
#define STAGE_W (32 * SROW)            // words per matrix per stage
#define GS_BYTES (4 * STAGE_W * 4)     // 2 stages x (A+B) = 67584 bytes

__global__ __launch_bounds__(256, 2) void gemm_qkv_kernel(
    const float* __restrict__ A,
    const float* __restrict__ W0, const float* __restrict__ W1,
    const float* __restrict__ W2,
    float* __restrict__ O0, float* __restrict__ O1, float* __restrict__ O2,
    int K, int actsel)
{
    extern __shared__ unsigned gsm[];
    const int tid = threadIdx.x;
    const int grp = blockIdx.x >> 1;
    const int bn  = (blockIdx.x & 1) * 128;
    const float* W   = (grp == 0) ? W0 : (grp == 1) ? W1 : W2;
    float*       Out = (grp == 0) ? O0 : (grp == 1) ? O1 : O2;
    const int act = (actsel >> grp) & 1;
    const size_t bm = (size_t)blockIdx.y * 128;

    const int lane = tid & 31, wid = tid >> 5;
    const int wm = (wid & 1) * 64;
    const int wn = (wid >> 1) * 32;
    const int qr = lane >> 2;
    const int qc = lane & 3;

    // staging assignment: thread -> (row, k-half) for both A and B tiles
    const int srow  = tid >> 1;
    const int shalf = tid & 1;
    const int sidx  = (srow & ~31) | ((srow & 7) << 2) | ((srow >> 3) & 3);
    const int sxi   = sidx ^ (shalf << 1);       // swizzled store index
    const int skb   = shalf * 16;
    const float* Ag = A + (bm + srow) * (size_t)K + skb;
    const float* Wg = W + (size_t)(bn + srow) * K + skb;

    const int NT = K >> 5;

    float acc[4][4][4];
    #pragma unroll
    for (int mf = 0; mf < 4; mf++)
        #pragma unroll
        for (int nf = 0; nf < 4; nf++)
            #pragma unroll
            for (int i = 0; i < 4; i++) acc[mf][nf][i] = 0.f;

    float4 ra[4], rw[4];

    // prologue: load + stage tile 0
    #pragma unroll
    for (int j = 0; j < 4; j++) {
        ra[j] = *(const float4*)(Ag + j * 4);
        rw[j] = *(const float4*)(Wg + j * 4);
    }
    {
        unsigned* Asm = gsm;
        unsigned* Bsm = gsm + STAGE_W;
        #pragma unroll
        for (int j = 0; j < 4; j++) {
            int k0 = (skb + j * 4) * SROW + sxi;
            Asm[k0]            = __float_as_uint(ra[j].x);
            Asm[k0 + SROW]     = __float_as_uint(ra[j].y);
            Asm[k0 + 2 * SROW] = __float_as_uint(ra[j].z);
            Asm[k0 + 3 * SROW] = __float_as_uint(ra[j].w);
            Bsm[k0]            = __float_as_uint(rw[j].x);
            Bsm[k0 + SROW]     = __float_as_uint(rw[j].y);
            Bsm[k0 + 2 * SROW] = __float_as_uint(rw[j].z);
            Bsm[k0 + 3 * SROW] = __float_as_uint(rw[j].w);
        }
    }
    __syncthreads();

    for (int kt = 0; kt < NT; kt++) {
        const bool more = (kt + 1 < NT);
        if (more) {
            const float* a = Ag + (kt + 1) * 32;
            const float* w = Wg + (kt + 1) * 32;
            #pragma unroll
            for (int j = 0; j < 4; j++) {
                ra[j] = *(const float4*)(a + j * 4);
                rw[j] = *(const float4*)(w + j * 4);
            }
        }

        const unsigned* Asm = gsm + (kt & 1) * (2 * STAGE_W);
        const unsigned* Bsm = Asm + STAGE_W;

        #pragma unroll
        for (int k8 = 0; k8 < 4; k8++) {
            const int kc = k8 * 8;
            const int sw = (kc >= 16) ? 2 : 0;   // compile-time register perm
            const int c1 = (kc + qc) * SROW;
            const int c2 = (kc + qc + 4) * SROW;

            uint4 vb1 = *(const uint4*)&Bsm[c1 + wn + qr * 4];
            uint4 vb2 = *(const uint4*)&Bsm[c2 + wn + qr * 4];
            uint4 lo1 = *(const uint4*)&Asm[c1 + wm + qr * 4];
            uint4 hi1 = *(const uint4*)&Asm[c1 + wm + 32 + qr * 4];
            uint4 lo2 = *(const uint4*)&Asm[c2 + wm + qr * 4];
            uint4 hi2 = *(const uint4*)&Asm[c2 + wm + 32 + qr * 4];

            const unsigned bu0[4] = {vb1.x, vb1.y, vb1.z, vb1.w};
            const unsigned bu1[4] = {vb2.x, vb2.y, vb2.z, vb2.w};
            const unsigned al1[4] = {lo1.x, lo1.y, lo1.z, lo1.w};
            const unsigned ah1[4] = {hi1.x, hi1.y, hi1.z, hi1.w};
            const unsigned al2[4] = {lo2.x, lo2.y, lo2.z, lo2.w};
            const unsigned ah2[4] = {hi2.x, hi2.y, hi2.z, hi2.w};

            #pragma unroll
            for (int mf = 0; mf < 4; mf++) {
                const unsigned* v1 = (mf < 2) ? al1 : ah1;
                const unsigned* v2 = (mf < 2) ? al2 : ah2;
                const unsigned a0 = v1[(2 * (mf & 1) + 0) ^ sw];
                const unsigned a1 = v1[(2 * (mf & 1) + 1) ^ sw];
                const unsigned a2 = v2[(2 * (mf & 1) + 0) ^ sw];
                const unsigned a3 = v2[(2 * (mf & 1) + 1) ^ sw];
                #pragma unroll
                for (int nf = 0; nf < 4; nf++) {
                    asm volatile(
                        "mma.sync.aligned.m16n8k8.row.col.f32.tf32.tf32.f32 "
                        "{%0,%1,%2,%3}, {%4,%5,%6,%7}, {%8,%9}, {%0,%1,%2,%3};"
                        : "+f"(acc[mf][nf][0]), "+f"(acc[mf][nf][1]),
                          "+f"(acc[mf][nf][2]), "+f"(acc[mf][nf][3])
                        : "r"(a0), "r"(a1), "r"(a2), "r"(a3),
                          "r"(bu0[nf ^ sw]), "r"(bu1[nf ^ sw]));
                }
            }
        }

        if (more) {
            unsigned* AsmN = gsm + ((kt + 1) & 1) * (2 * STAGE_W);
            unsigned* BsmN = AsmN + STAGE_W;
            #pragma unroll
            for (int j = 0; j < 4; j++) {
                int k0 = (skb + j * 4) * SROW + sxi;
                AsmN[k0]            = __float_as_uint(ra[j].x);
                AsmN[k0 + SROW]     = __float_as_uint(ra[j].y);
                AsmN[k0 + 2 * SROW] = __float_as_uint(ra[j].z);
                AsmN[k0 + 3 * SROW] = __float_as_uint(ra[j].w);
                BsmN[k0]            = __float_as_uint(rw[j].x);
                BsmN[k0 + SROW]     = __float_as_uint(rw[j].y);
                BsmN[k0 + 2 * SROW] = __float_as_uint(rw[j].z);
                BsmN[k0 + 3 * SROW] = __float_as_uint(rw[j].w);
            }
        }
        __syncthreads();
    }

    #pragma unroll
    for (int mf = 0; mf < 4; mf++) {
        size_t r0 = bm + wm + mf * 16 + qr;
        #pragma unroll
        for (int nf = 0; nf < 4; nf++) {
            int col = bn + wn + nf * 8 + qc * 2;
            float c0 = acc[mf][nf][0], c1 = acc[mf][nf][1];
            float c2 = acc[mf][nf][2], c3 = acc[mf][nf][3];
            if (act) {
                c0 = 1.0f / (1.0f + __expf(-c0));
                c1 = 1.0f / (1.0f + __expf(-c1));
                c2 = 1.0f / (1.0f + __expf(-c2));
                c3 = 1.0f / (1.0f + __expf(-c3));
            }
            *(float2*)(Out + r0 * 256 + col)       = make_float2(c0, c1);
            *(float2*)(Out + (r0 + 8) * 256 + col) = make_float2(c2, c3);
        }
    }
}

// ---------------- 4) WKV chunk-parallel scan ---------------------------------
__device__ __forceinline__ void wkv_state(float kt, float vt, float wdec,
                                          float& a, float& b, float& pp)
{
    float ww2 = pp + wdec;
    float d2  = ww2 - kt;
    float f   = __expf(-fabsf(d2));
    float f1  = (d2 >= 0.f) ? 1.f : f;
    float f2  = (d2 >= 0.f) ? f : 1.f;
    a  = f1 * a + f2 * vt;
    b  = f1 * b + f2;
    pp = fmaxf(ww2, kt);
}

__global__ __launch_bounds__(256) void wkv_pass1(const float* __restrict__ sd)
{
    int g     = blockIdx.x * 256 + threadIdx.x;
    int chain = g & (NCHAIN - 1);
    int chunk = g >> 12;
    int b = chain >> 9;
    int d = chain & 511;
    int c = d & 255;
    bool second = d >= 256;

    float wdec = -__expf(sd[d] * (1.0f / (float)TT));
    const size_t base = (size_t)b * TT * CC + c;

    float a = 0.f, bb = 0.f, pp = -1e38f;
    int tstart = chunk * CHLEN;

    for (int t0 = tstart; t0 < tstart + CHLEN; t0 += 8) {
        float kb[8], vb[8];
        #pragma unroll
        for (int i = 0; i < 8; i++) {
            int t  = t0 + i;
            int ti = second ? (((t & 63) << 6) | (t >> 6)) : t;
            size_t off = base + (size_t)ti * CC;
            kb[i] = g_k[off];
            vb[i] = g_v[off];
        }
        #pragma unroll
        for (int i = 0; i < 8; i++)
            wkv_state(kb[i], vb[i], wdec, a, bb, pp);
    }
    g_sa[chunk * NCHAIN + chain] = a;
    g_sb[chunk * NCHAIN + chain] = bb;
    g_sp[chunk * NCHAIN + chain] = pp;
}

__global__ __launch_bounds__(256) void wkv_pass2(const float* __restrict__ sd)
{
    int chain = blockIdx.x * 256 + threadIdx.x;
    int d = chain & 511;
    float wdec = -__expf(sd[d] * (1.0f / (float)TT));
    float Lw = (float)CHLEN * wdec;

    float A = 0.f, B = 0.f, P = -1e38f;
    for (int j = 0; j < NCHUNK; j++) {
        g_pa[j * NCHAIN + chain] = A;
        g_pb[j * NCHAIN + chain] = B;
        g_pp[j * NCHAIN + chain] = P;
        float ca = g_sa[j * NCHAIN + chain];
        float cb = g_sb[j * NCHAIN + chain];
        float cp = g_sp[j * NCHAIN + chain];
        float np = P + Lw;
        float p  = fmaxf(np, cp);
        float e1 = __expf(np - p);
        float e2 = __expf(cp - p);
        A = e1 * A + e2 * ca;
        B = e1 * B + e2 * cb;
        P = p;
    }
}

__global__ __launch_bounds__(256) void wkv_pass3(const float* __restrict__ sd,
                                                 const float* __restrict__ sf)
{
    int g     = blockIdx.x * 256 + threadIdx.x;
    int chain = g & (NCHAIN - 1);
    int chunk = g >> 12;
    int b = chain >> 9;
    int d = chain & 511;
    int c = d & 255;
    bool second = d >= 256;

    float wdec = -__expf(sd[d] * (1.0f / (float)TT));
    float u    =  sf[d] * (1.0f / (float)TT);

    const size_t base = (size_t)b * TT * CC + c;
    float* xsp = g_xs + (size_t)b * TT * DD + d;

    float a  = g_pa[chunk * NCHAIN + chain];
    float bb = g_pb[chunk * NCHAIN + chain];
    float pp = g_pp[chunk * NCHAIN + chain];

    int tstart = chunk * CHLEN;
    for (int t0 = tstart; t0 < tstart + CHLEN; t0 += 8) {
        float kb[8], vb[8], sb[8];
        #pragma unroll
        for (int i = 0; i < 8; i++) {
            int t  = t0 + i;
            int ti = second ? (((t & 63) << 6) | (t >> 6)) : t;
            size_t off = base + (size_t)ti * CC;
            kb[i] = g_k[off];
            vb[i] = g_v[off];
            sb[i] = g_sr[base + (size_t)t * CC];
        }
        #pragma unroll
        for (int i = 0; i < 8; i++) {
            float kt = kb[i], vt = vb[i];
            float ww = u + kt;
            float d1 = pp - ww;
            float e  = __expf(-fabsf(d1));
            float e1 = (d1 >= 0.f) ? 1.f : e;
            float e2 = (d1 >= 0.f) ? e : 1.f;
            float out = __fdividef(e1 * a + e2 * vt, e1 * bb + e2);
            wkv_state(kt, vt, wdec, a, bb, pp);
            xsp[(size_t)(t0 + i) * DD] = rnd_tf32(out * sb[i]);
        }
    }
}

// ---------------- launch -----------------------------------------------------
extern "C" void kernel_launch(void* const* d_in, const int* in_sizes, int n_in,
                              void* d_out, int out_size)
{
    const float* x     = (const float*)d_in[0];
    const float* alpha = (const float*)d_in[1];
    const float* cw1   = (const float*)d_in[2];
    const float* cw3   = (const float*)d_in[3];
    const float* cw5   = (const float*)d_in[4];
    const float* Wk    = (const float*)d_in[5];
    const float* Wv    = (const float*)d_in[6];
    const float* Wr    = (const float*)d_in[7];
    const float* Wo    = (const float*)d_in[8];
    const float* sd    = (const float*)d_in[9];
    const float* sf    = (const float*)d_in[10];

    float *xf, *k, *v, *sr, *xs, *wk, *wv, *wr, *wo;
    cudaGetSymbolAddress((void**)&xf, g_xf);
    cudaGetSymbolAddress((void**)&k,  g_k);
    cudaGetSymbolAddress((void**)&v,  g_v);
    cudaGetSymbolAddress((void**)&sr, g_sr);
    cudaGetSymbolAddress((void**)&xs, g_xs);
    cudaGetSymbolAddress((void**)&wk, g_wk);
    cudaGetSymbolAddress((void**)&wv, g_wv);
    cudaGetSymbolAddress((void**)&wr, g_wr);
    cudaGetSymbolAddress((void**)&wo, g_wo);

    cudaFuncSetAttribute(gemm_qkv_kernel,
                         cudaFuncAttributeMaxDynamicSharedMemorySize, GS_BYTES);

    round_weights_kernel<<<(CC * DD + 255) / 256, 256>>>(Wk, Wv, Wr, Wo);
    combine_weights_kernel<<<1, 256>>>(alpha, cw1, cw3, cw5);
    omni_conv_kernel<<<BATCH * WW_, 256>>>(x);

    // fused k / v / r(sigmoid) gemms: grid.x = 6 (3 groups x 2 n-blocks)
    dim3 g3(6, MM / 128);
    gemm_qkv_kernel<<<g3, 256, GS_BYTES>>>(xf, wk, wv, wr, k, v, sr, CC, 4);

    wkv_pass1<<<(NCHAIN * NCHUNK) / 256, 256>>>(sd);
    wkv_pass2<<<NCHAIN / 256, 256>>>(sd);
    wkv_pass3<<<(NCHAIN * NCHUNK) / 256, 256>>>(sd, sf);

    // output projection: grid.x = 2 (group 0 only)
    dim3 g1(2, MM / 128);
    gemm_qkv_kernel<<<g1, 256, GS_BYTES>>>(xs, wo, wo, wo,
                                           (float*)d_out, (float*)d_out,
                                           (float*)d_out, DD, 0);
}